// round 1
// baseline (speedup 1.0000x reference)
#include <cuda_runtime.h>
#include <math.h>

#define Bb   64
#define Tt   2048
#define ENC  512
#define DEC  1024
#define CONVC 32
#define KW   31
#define HID  256
#define PADW 15

#define BT 64      // t-tile per block
#define KC 32      // k-chunk
#define NSEG 16    // att_c segments

// ---- scratch (no allocations allowed) ----
__device__ float g_dec[Bb * HID];          // dec_state @ W_dec^T
__device__ float g_g[KW * HID];            // g[k][h] = sum_c conv_w[c,k]*W_att[h,c]
__device__ float g_energy[Bb * Tt];        // pre-softmax energies
__device__ float g_part[NSEG * Bb * ENC];  // att_c partial sums

// ============================================================
// dec[b,h] = sum_c dec_state[b,c] * W_dec[h,c]   (warp per h)
// ============================================================
__global__ void dec_kernel(const float* __restrict__ dec_state,
                           const float* __restrict__ Wdec) {
    int b = blockIdx.x;
    int warp = threadIdx.x >> 5, lane = threadIdx.x & 31;
    for (int h = warp; h < HID; h += 8) {
        float s = 0.f;
        const float* xr = dec_state + (size_t)b * DEC;
        const float* wr = Wdec + (size_t)h * DEC;
        for (int c = lane * 4; c < DEC; c += 32 * 4) {
            float4 x = *(const float4*)&xr[c];
            float4 w = *(const float4*)&wr[c];
            s += x.x * w.x + x.y * w.y + x.z * w.z + x.w * w.w;
        }
        #pragma unroll
        for (int off = 16; off > 0; off >>= 1)
            s += __shfl_xor_sync(0xFFFFFFFFu, s, off);
        if (lane == 0) g_dec[b * HID + h] = s;
    }
}

// ============================================================
// g[k][h] = sum_c W_att[h,c] * conv_w[c,0,k]
// ============================================================
__global__ void g_kernel(const float* __restrict__ Watt,
                         const float* __restrict__ convw) {
    int h = threadIdx.x;  // 256 threads
    for (int k = 0; k < KW; k++) {
        float s = 0.f;
        #pragma unroll 8
        for (int c = 0; c < CONVC; c++)
            s += Watt[h * CONVC + c] * convw[c * KW + k];
        g_g[k * HID + h] = s;
    }
}

// ============================================================
// Fused energy kernel:
// energy[b,t] = w_b + sum_h w_w[h]*tanh( [enc|prev_window] @ [W_enc|g]^T
//                                         + b_enc[h] + dec[b,h] )
// block: 256 threads -> 64 t x 256 h tile, K = 512 (16 chunks) + 1 conv chunk
// ============================================================
__global__ __launch_bounds__(256)
void energy_kernel(const float* __restrict__ enc,
                   const float* __restrict__ Wenc,
                   const float* __restrict__ benc,
                   const float* __restrict__ prev,
                   const float* __restrict__ ww,
                   const float* __restrict__ wb) {
    __shared__ __align__(16) float encS[KC][68];   // [k][t], padded rows (272B, 16B-mult)
    __shared__ __align__(16) float wS[KC][260];    // [k][h], padded rows (1040B, 16B-mult)
    __shared__ float red[BT][17];

    const int b  = blockIdx.y;
    const int t0 = blockIdx.x * BT;
    const int tid = threadIdx.x;
    const int tx = tid & 15;   // h-group: h = tx*16 + j
    const int ty = tid >> 4;   // t-group: t = ty*4 + i

    float acc[4][16];
    #pragma unroll
    for (int i = 0; i < 4; i++)
        #pragma unroll
        for (int j = 0; j < 16; j++) acc[i][j] = 0.f;

    const int k4 = tid & 7;        // float4 index within 32-wide k chunk
    const int rA = tid >> 3;       // 0..31

    for (int ch = 0; ch < 17; ch++) {
        __syncthreads();
        if (ch < 16) {
            const int k0 = ch * KC;
            // enc tile: 64 t-rows x 32 k  (coalesced float4, transposed store)
            #pragma unroll
            for (int p = 0; p < 2; p++) {
                int t = rA + p * 32;
                float4 v = *(const float4*)&enc[((size_t)b * Tt + t0 + t) * ENC + k0 + k4 * 4];
                encS[k4 * 4 + 0][t] = v.x;
                encS[k4 * 4 + 1][t] = v.y;
                encS[k4 * 4 + 2][t] = v.z;
                encS[k4 * 4 + 3][t] = v.w;
            }
            // W_enc tile: 256 h-rows x 32 k
            #pragma unroll
            for (int p = 0; p < 8; p++) {
                int h = rA + p * 32;
                float4 v = *(const float4*)&Wenc[(size_t)h * ENC + k0 + k4 * 4];
                wS[k4 * 4 + 0][h] = v.x;
                wS[k4 * 4 + 1][h] = v.y;
                wS[k4 * 4 + 2][h] = v.z;
                wS[k4 * 4 + 3][h] = v.w;
            }
        } else {
            // conv chunk: A cols = shifted prev window, B cols = g
            for (int idx = tid; idx < KC * BT; idx += 256) {
                int k = idx >> 6, t = idx & 63;
                int src = t0 + t + k - PADW;
                encS[k][t] = (k < KW && src >= 0 && src < Tt)
                                 ? prev[b * Tt + src] : 0.f;
            }
            for (int idx = tid; idx < KC * HID; idx += 256) {
                int k = idx >> 8, h = idx & 255;
                wS[k][h] = (k < KW) ? g_g[k * HID + h] : 0.f;
            }
        }
        __syncthreads();

        #pragma unroll
        for (int kk = 0; kk < KC; kk++) {
            float4 av4 = *(const float4*)&encS[kk][ty * 4];
            float av[4] = {av4.x, av4.y, av4.z, av4.w};
            float bv[16];
            #pragma unroll
            for (int q = 0; q < 4; q++)
                *(float4*)&bv[q * 4] = *(const float4*)&wS[kk][tx * 16 + q * 4];
            #pragma unroll
            for (int i = 0; i < 4; i++)
                #pragma unroll
                for (int j = 0; j < 16; j++)
                    acc[i][j] = fmaf(av[i], bv[j], acc[i][j]);
        }
    }

    // epilogue: + b_enc + dec, tanh, dot w_w
    float wreg[16], dreg[16], breg[16];
    #pragma unroll
    for (int j = 0; j < 16; j++) {
        int h = tx * 16 + j;
        wreg[j] = ww[h];
        dreg[j] = g_dec[b * HID + h];
        breg[j] = benc[h];
    }
    #pragma unroll
    for (int i = 0; i < 4; i++) {
        float e = 0.f;
        #pragma unroll
        for (int j = 0; j < 16; j++)
            e += wreg[j] * tanhf(acc[i][j] + dreg[j] + breg[j]);
        red[ty * 4 + i][tx] = e;
    }
    __syncthreads();
    if (tid < BT) {
        float s = wb[0];
        #pragma unroll
        for (int x = 0; x < 16; x++) s += red[tid][x];
        g_energy[b * Tt + t0 + tid] = s;
    }
}

// ============================================================
// masked softmax over T per batch; writes att_w into out
// ============================================================
__global__ void softmax_kernel(const int* __restrict__ text_len,
                               float* __restrict__ out_w) {
    const int b = blockIdx.x;
    const int tid = threadIdx.x;
    const int len = text_len[b];
    __shared__ float sh[256];

    float m = -3.402823466e+38f;
    for (int t = tid; t < Tt; t += 256)
        if (t < len) m = fmaxf(m, g_energy[b * Tt + t]);
    sh[tid] = m; __syncthreads();
    for (int s = 128; s > 0; s >>= 1) {
        if (tid < s) sh[tid] = fmaxf(sh[tid], sh[tid + s]);
        __syncthreads();
    }
    const float M = sh[0];
    __syncthreads();

    float sum = 0.f;
    for (int t = tid; t < Tt; t += 256) {
        float e = (t < len) ? __expf(g_energy[b * Tt + t] - M) : 0.f;
        out_w[b * Tt + t] = e;
        sum += e;
    }
    sh[tid] = sum; __syncthreads();
    for (int s = 128; s > 0; s >>= 1) {
        if (tid < s) sh[tid] += sh[tid + s];
        __syncthreads();
    }
    const float inv = 1.f / sh[0];
    for (int t = tid; t < Tt; t += 256)
        out_w[b * Tt + t] *= inv;
}

// ============================================================
// att_c partials: seg covers T/NSEG timesteps (deterministic, no atomics)
// ============================================================
__global__ void attc_part_kernel(const float* __restrict__ enc,
                                 const float* __restrict__ att_w) {
    const int b = blockIdx.y, seg = blockIdx.x;
    const int c = threadIdx.x;  // 512
    const int tstart = seg * (Tt / NSEG);
    float s = 0.f;
    for (int t = tstart; t < tstart + (Tt / NSEG); t++)
        s = fmaf(enc[((size_t)b * Tt + t) * ENC + c], att_w[b * Tt + t], s);
    g_part[(seg * Bb + b) * ENC + c] = s;
}

__global__ void attc_reduce_kernel(float* __restrict__ out_c) {
    const int b = blockIdx.x;
    const int c = threadIdx.x;  // 512
    float s = 0.f;
    #pragma unroll
    for (int seg = 0; seg < NSEG; seg++)
        s += g_part[(seg * Bb + b) * ENC + c];
    out_c[b * ENC + c] = s;
}

// ============================================================
extern "C" void kernel_launch(void* const* d_in, const int* in_sizes, int n_in,
                              void* d_out, int out_size) {
    const float* enc       = (const float*)d_in[0];   // (B,T,ENC)
    const float* dec_state = (const float*)d_in[1];   // (B,DEC)
    const float* prev      = (const float*)d_in[2];   // (B,T)
    const int*   text_len  = (const int*)  d_in[3];   // (B,)
    const float* Wenc      = (const float*)d_in[4];   // (HID,ENC)
    const float* benc      = (const float*)d_in[5];   // (HID,)
    const float* Wdec      = (const float*)d_in[6];   // (HID,DEC)
    const float* Watt      = (const float*)d_in[7];   // (HID,CONV)
    const float* convw     = (const float*)d_in[8];   // (CONV,1,K)
    const float* ww        = (const float*)d_in[9];   // (1,HID)
    const float* wb        = (const float*)d_in[10];  // (1,)

    float* out   = (float*)d_out;
    float* out_c = out;                 // att_c: (B,ENC)
    float* out_w = out + Bb * ENC;      // att_w: (B,T)

    dec_kernel<<<Bb, 256>>>(dec_state, Wdec);
    g_kernel<<<1, 256>>>(Watt, convw);
    energy_kernel<<<dim3(Tt / BT, Bb), 256>>>(enc, Wenc, benc, prev, ww, wb);
    softmax_kernel<<<Bb, 256>>>(text_len, out_w);
    attc_part_kernel<<<dim3(NSEG, Bb), ENC>>>(enc, out_w);
    attc_reduce_kernel<<<Bb, ENC>>>(out_c);
}

// round 5
// speedup vs baseline: 3.8377x; 3.8377x over previous
#include <cuda_runtime.h>
#include <cuda_bf16.h>
#include <math.h>
#include <stdint.h>

#define Bb    64
#define Tt    2048
#define ENC   512
#define DEC   1024
#define CONVC 32
#define KW    31
#define HID   256
#define PADW  15

#define KTOT   576            // 512 enc + 31 conv + 33 zero pad
#define KSTEPS 36             // KTOT / 16
#define NT8    32             // n8 tiles across N=256
#define NSEG   16

// ---------------- device scratch ----------------
__device__ float g_dbc[Bb * HID];                 // dec@Wdec^T + b_enc
__device__ uint4 g_Bpack[KSTEPS * NT8 * 32];      // fragment-packed weights (hi/lo)
__device__ float g_energy[Bb * Tt];
__device__ float g_part[NSEG * Bb * ENC];

// ---------------- helpers ----------------
__device__ __forceinline__ void packhl(float x, float y, uint32_t& hi, uint32_t& lo) {
    __nv_bfloat16 xh = __float2bfloat16(x), yh = __float2bfloat16(y);
    __nv_bfloat16 xl = __float2bfloat16(x - __bfloat162float(xh));
    __nv_bfloat16 yl = __float2bfloat16(y - __bfloat162float(yh));
    hi = (uint32_t)__bfloat16_as_ushort(xh) | ((uint32_t)__bfloat16_as_ushort(yh) << 16);
    lo = (uint32_t)__bfloat16_as_ushort(xl) | ((uint32_t)__bfloat16_as_ushort(yl) << 16);
}

__device__ __forceinline__ void mma16816(float* d, const uint32_t* a,
                                         uint32_t b0, uint32_t b1) {
    asm volatile(
        "mma.sync.aligned.m16n8k16.row.col.f32.bf16.bf16.f32 "
        "{%0,%1,%2,%3}, {%4,%5,%6,%7}, {%8,%9}, {%0,%1,%2,%3};"
        : "+f"(d[0]), "+f"(d[1]), "+f"(d[2]), "+f"(d[3])
        : "r"(a[0]), "r"(a[1]), "r"(a[2]), "r"(a[3]), "r"(b0), "r"(b1));
}

// ============================================================
// prep: dbc[b,h] = dec_state[b]·W_dec[h] + b_enc[h]
// ============================================================
__global__ void dbc_kernel(const float* __restrict__ dec_state,
                           const float* __restrict__ Wdec,
                           const float* __restrict__ benc) {
    int b = blockIdx.x;
    int warp = threadIdx.x >> 5, lane = threadIdx.x & 31;
    for (int h = warp; h < HID; h += 8) {
        float s = 0.f;
        const float* xr = dec_state + (size_t)b * DEC;
        const float* wr = Wdec + (size_t)h * DEC;
        for (int c = lane * 4; c < DEC; c += 32 * 4) {
            float4 x = *(const float4*)&xr[c];
            float4 w = *(const float4*)&wr[c];
            s += x.x * w.x + x.y * w.y + x.z * w.z + x.w * w.w;
        }
        #pragma unroll
        for (int off = 16; off > 0; off >>= 1) s += __shfl_xor_sync(0xFFFFFFFFu, s, off);
        if (lane == 0) g_dbc[b * HID + h] = s + benc[h];
    }
}

// ============================================================
// prep: pack Wext = [W_enc | g | 0] into per-lane mma fragment order
// g_Bpack[(s*NT8 + j)*32 + lane] = {b0_hi, b1_hi, b0_lo, b1_lo}
// where h = j*8 + (lane>>2), k = s*16 + (lane&3)*2 (b0: k,k+1; b1: k+8,k+9)
// ============================================================
__device__ __forceinline__ float wval(const float* Wenc, const float* Watt,
                                      const float* convw, int h, int col) {
    if (col < ENC) return Wenc[(size_t)h * ENC + col];
    int cc = col - ENC;
    if (cc < KW) {
        float s = 0.f;
        #pragma unroll
        for (int c = 0; c < CONVC; c++) s += Watt[h * CONVC + c] * convw[c * KW + cc];
        return s;
    }
    return 0.f;
}

__global__ void bpack_kernel(const float* __restrict__ Wenc,
                             const float* __restrict__ Watt,
                             const float* __restrict__ convw) {
    int idx = blockIdx.x * 256 + threadIdx.x;
    if (idx >= KSTEPS * NT8 * 32) return;
    int lane = idx & 31, j = (idx >> 5) & 31, s = idx >> 10;
    int h = j * 8 + (lane >> 2);
    int k = s * 16 + (lane & 3) * 2;
    float v0 = wval(Wenc, Watt, convw, h, k);
    float v1 = wval(Wenc, Watt, convw, h, k + 1);
    float v8 = wval(Wenc, Watt, convw, h, k + 8);
    float v9 = wval(Wenc, Watt, convw, h, k + 9);
    uint4 r;
    packhl(v0, v1, r.x, r.z);
    packhl(v8, v9, r.y, r.w);
    g_Bpack[idx] = r;
}

// ============================================================
// energy kernel: CTA = 64 t-rows x 256 h; 8 warps (2 M x 4 N)
// ============================================================
__global__ __launch_bounds__(256, 1)
void energy_kernel(const float* __restrict__ enc,
                   const float* __restrict__ prev,
                   const float* __restrict__ ww,
                   const float* __restrict__ wb) {
    __shared__ float wwS[HID], dbS[HID];
    __shared__ float redS[64][5];

    const int tid = threadIdx.x;
    const int b = blockIdx.y, t0 = blockIdx.x * 64;
    const int warp = tid >> 5, lane = tid & 31;
    const int warp_m = warp >> 2, warp_n = warp & 3;
    const int g = lane >> 2, tq = lane & 3;

    if (tid < HID) {
        wwS[tid] = ww[tid];
        dbS[tid] = g_dbc[b * HID + tid];
    }
    __syncthreads();

    float d[2][8][4];
    #pragma unroll
    for (int mi = 0; mi < 2; mi++)
        #pragma unroll
        for (int jj = 0; jj < 8; jj++)
            #pragma unroll
            for (int q = 0; q < 4; q++) d[mi][jj][q] = 0.f;

    const int r_base = t0 + warp_m * 32;         // + mi*16 + g (+8)
    const float* encB = enc + (size_t)b * Tt * ENC;

    // ---- main K loop over enc (s = 0..31) ----
    for (int s = 0; s < 32; s++) {
        const int k0 = s * 16 + tq * 2;          // b0 cols; b1 at +8
        uint32_t ahi[2][4], alo[2][4];
        #pragma unroll
        for (int mi = 0; mi < 2; mi++) {
            const int r0 = r_base + mi * 16 + g;
            float2 v;
            v = *(const float2*)&encB[(size_t)r0 * ENC + k0];
            packhl(v.x, v.y, ahi[mi][0], alo[mi][0]);
            v = *(const float2*)&encB[(size_t)(r0 + 8) * ENC + k0];
            packhl(v.x, v.y, ahi[mi][1], alo[mi][1]);
            v = *(const float2*)&encB[(size_t)r0 * ENC + k0 + 8];
            packhl(v.x, v.y, ahi[mi][2], alo[mi][2]);
            v = *(const float2*)&encB[(size_t)(r0 + 8) * ENC + k0 + 8];
            packhl(v.x, v.y, ahi[mi][3], alo[mi][3]);
        }
        uint4 Bf[8];
        #pragma unroll
        for (int jj = 0; jj < 8; jj++)
            Bf[jj] = g_Bpack[(s * NT8 + warp_n * 8 + jj) * 32 + lane];
        #pragma unroll
        for (int mi = 0; mi < 2; mi++)
            #pragma unroll
            for (int jj = 0; jj < 8; jj++) {
                mma16816(d[mi][jj], ahi[mi], Bf[jj].x, Bf[jj].y);  // hi*hi
                mma16816(d[mi][jj], ahi[mi], Bf[jj].z, Bf[jj].w);  // hi*lo
                mma16816(d[mi][jj], alo[mi], Bf[jj].x, Bf[jj].y);  // lo*hi
            }
    }

    // ---- conv K chunk (s = 32..35): A cols are shifted prev window ----
    const float* prevB = prev + b * Tt;
    for (int s = 32; s < KSTEPS; s++) {
        const int k0 = s * 16 + tq * 2;
        uint32_t ahi[2][4], alo[2][4];
        #pragma unroll
        for (int mi = 0; mi < 2; mi++) {
            #pragma unroll
            for (int q = 0; q < 4; q++) {
                const int row = r_base + mi * 16 + g + ((q & 1) ? 8 : 0);
                const int col = k0 + ((q >= 2) ? 8 : 0);
                float x = 0.f, y = 0.f;
                int cc = col - ENC;
                if (cc < KW) {
                    int src = row + cc - PADW;
                    if (src >= 0 && src < Tt) x = prevB[src];
                }
                if (cc + 1 < KW) {
                    int src = row + cc + 1 - PADW;
                    if (src >= 0 && src < Tt) y = prevB[src];
                }
                packhl(x, y, ahi[mi][q], alo[mi][q]);
            }
        }
        uint4 Bf[8];
        #pragma unroll
        for (int jj = 0; jj < 8; jj++)
            Bf[jj] = g_Bpack[(s * NT8 + warp_n * 8 + jj) * 32 + lane];
        #pragma unroll
        for (int mi = 0; mi < 2; mi++)
            #pragma unroll
            for (int jj = 0; jj < 8; jj++) {
                mma16816(d[mi][jj], ahi[mi], Bf[jj].x, Bf[jj].y);
                mma16816(d[mi][jj], ahi[mi], Bf[jj].z, Bf[jj].w);
                mma16816(d[mi][jj], alo[mi], Bf[jj].x, Bf[jj].y);
            }
    }

    // ---- epilogue: e(row) = sum_h ww[h]*tanh(C + dbc[h]) ----
    float ww0[8], ww1[8], db0[8], db1[8];
    #pragma unroll
    for (int jj = 0; jj < 8; jj++) {
        int h = warp_n * 64 + jj * 8 + tq * 2;
        ww0[jj] = wwS[h];     ww1[jj] = wwS[h + 1];
        db0[jj] = dbS[h];     db1[jj] = dbS[h + 1];
    }
    #pragma unroll
    for (int mi = 0; mi < 2; mi++) {
        #pragma unroll
        for (int half = 0; half < 2; half++) {
            float e = 0.f;
            #pragma unroll
            for (int jj = 0; jj < 8; jj++) {
                e += ww0[jj] * tanhf(d[mi][jj][half * 2 + 0] + db0[jj]);
                e += ww1[jj] * tanhf(d[mi][jj][half * 2 + 1] + db1[jj]);
            }
            e += __shfl_xor_sync(0xFFFFFFFFu, e, 1);
            e += __shfl_xor_sync(0xFFFFFFFFu, e, 2);
            if (tq == 0)
                redS[warp_m * 32 + mi * 16 + half * 8 + g][warp_n] = e;
        }
    }
    __syncthreads();
    if (tid < 64) {
        float e = redS[tid][0] + redS[tid][1] + redS[tid][2] + redS[tid][3];
        g_energy[b * Tt + t0 + tid] = e + wb[0];
    }
}

// ============================================================
// masked softmax over T per batch; writes att_w into out
// ============================================================
__global__ void softmax_kernel(const int* __restrict__ text_len,
                               float* __restrict__ out_w) {
    const int b = blockIdx.x;
    const int tid = threadIdx.x;
    const int len = text_len[b];
    __shared__ float sh[256];

    float m = -3.402823466e+38f;
    for (int t = tid; t < Tt; t += 256)
        if (t < len) m = fmaxf(m, g_energy[b * Tt + t]);
    sh[tid] = m; __syncthreads();
    for (int s = 128; s > 0; s >>= 1) {
        if (tid < s) sh[tid] = fmaxf(sh[tid], sh[tid + s]);
        __syncthreads();
    }
    const float M = sh[0];
    __syncthreads();

    float sum = 0.f;
    for (int t = tid; t < Tt; t += 256) {
        float e = (t < len) ? __expf(g_energy[b * Tt + t] - M) : 0.f;
        out_w[b * Tt + t] = e;
        sum += e;
    }
    sh[tid] = sum; __syncthreads();
    for (int s = 128; s > 0; s >>= 1) {
        if (tid < s) sh[tid] += sh[tid + s];
        __syncthreads();
    }
    const float inv = 1.f / sh[0];
    for (int t = tid; t < Tt; t += 256)
        out_w[b * Tt + t] *= inv;
}

// ============================================================
// att_c: deterministic two-stage reduction
// ============================================================
__global__ void attc_part_kernel(const float* __restrict__ enc,
                                 const float* __restrict__ att_w) {
    const int b = blockIdx.y, seg = blockIdx.x;
    const int c = threadIdx.x;  // 512
    const int tstart = seg * (Tt / NSEG);
    float s = 0.f;
    for (int t = tstart; t < tstart + (Tt / NSEG); t++)
        s = fmaf(enc[((size_t)b * Tt + t) * ENC + c], att_w[b * Tt + t], s);
    g_part[(seg * Bb + b) * ENC + c] = s;
}

__global__ void attc_reduce_kernel(float* __restrict__ out_c) {
    const int b = blockIdx.x;
    const int c = threadIdx.x;  // 512
    float s = 0.f;
    #pragma unroll
    for (int seg = 0; seg < NSEG; seg++)
        s += g_part[(seg * Bb + b) * ENC + c];
    out_c[b * ENC + c] = s;
}

// ============================================================
extern "C" void kernel_launch(void* const* d_in, const int* in_sizes, int n_in,
                              void* d_out, int out_size) {
    const float* enc       = (const float*)d_in[0];   // (B,T,ENC)
    const float* dec_state = (const float*)d_in[1];   // (B,DEC)
    const float* prev      = (const float*)d_in[2];   // (B,T)
    const int*   text_len  = (const int*)  d_in[3];   // (B,)
    const float* Wenc      = (const float*)d_in[4];   // (HID,ENC)
    const float* benc      = (const float*)d_in[5];   // (HID,)
    const float* Wdec      = (const float*)d_in[6];   // (HID,DEC)
    const float* Watt      = (const float*)d_in[7];   // (HID,CONV)
    const float* convw     = (const float*)d_in[8];   // (CONV,1,K)
    const float* ww        = (const float*)d_in[9];   // (1,HID)
    const float* wb        = (const float*)d_in[10];  // (1,)

    float* out   = (float*)d_out;
    float* out_c = out;                 // att_c: (B,ENC)
    float* out_w = out + Bb * ENC;      // att_w: (B,T)

    dbc_kernel<<<Bb, 256>>>(dec_state, Wdec, benc);
    bpack_kernel<<<(KSTEPS * NT8 * 32 + 255) / 256, 256>>>(Wenc, Watt, convw);
    energy_kernel<<<dim3(Tt / 64, Bb), 256>>>(enc, prev, ww, wb);
    softmax_kernel<<<Bb, 256>>>(text_len, out_w);
    attc_part_kernel<<<dim3(NSEG, Bb), ENC>>>(enc, out_w);
    attc_reduce_kernel<<<Bb, ENC>>>(out_c);
}

// round 6
// speedup vs baseline: 7.1763x; 1.8700x over previous
#include <cuda_runtime.h>
#include <cuda_fp16.h>
#include <math.h>
#include <stdint.h>

#define Bb    64
#define Tt    2048
#define ENC   512
#define DEC   1024
#define CONVC 32
#define KW    31
#define HID   256
#define PADW  15

#define KTOT   576            // 512 enc + 31 conv + 33 zero pad
#define KSTEPS 36             // KTOT / 16
#define NT8    32             // n8 tiles across N=256
#define NSEG   16

// ---------------- device scratch ----------------
__device__ float g_dbc[Bb * HID];                 // dec@Wdec^T + b_enc
__device__ uint2 g_Bpack[KSTEPS * NT8 * 32];      // fp16 fragment-packed weights
__device__ float g_energy[Bb * Tt];
__device__ float g_part[NSEG * Bb * ENC];

// ---------------- helpers ----------------
__device__ __forceinline__ uint32_t packh(float x, float y) {
    __half2 h = __floats2half2_rn(x, y);
    return *(uint32_t*)&h;
}

__device__ __forceinline__ void mma16816(float* d, const uint32_t* a,
                                         uint32_t b0, uint32_t b1) {
    asm volatile(
        "mma.sync.aligned.m16n8k16.row.col.f32.f16.f16.f32 "
        "{%0,%1,%2,%3}, {%4,%5,%6,%7}, {%8,%9}, {%0,%1,%2,%3};"
        : "+f"(d[0]), "+f"(d[1]), "+f"(d[2]), "+f"(d[3])
        : "r"(a[0]), "r"(a[1]), "r"(a[2]), "r"(a[3]), "r"(b0), "r"(b1));
}

// ============================================================
// prep: dbc[b,h] = dec_state[b]·W_dec[h] + b_enc[h]
// ============================================================
__global__ void dbc_kernel(const float* __restrict__ dec_state,
                           const float* __restrict__ Wdec,
                           const float* __restrict__ benc) {
    int b = blockIdx.x;
    int warp = threadIdx.x >> 5, lane = threadIdx.x & 31;
    for (int h = warp; h < HID; h += 8) {
        float s = 0.f;
        const float* xr = dec_state + (size_t)b * DEC;
        const float* wr = Wdec + (size_t)h * DEC;
        for (int c = lane * 4; c < DEC; c += 32 * 4) {
            float4 x = *(const float4*)&xr[c];
            float4 w = *(const float4*)&wr[c];
            s += x.x * w.x + x.y * w.y + x.z * w.z + x.w * w.w;
        }
        #pragma unroll
        for (int off = 16; off > 0; off >>= 1) s += __shfl_xor_sync(0xFFFFFFFFu, s, off);
        if (lane == 0) g_dbc[b * HID + h] = s + benc[h];
    }
}

// ============================================================
// prep: pack Wext = [W_enc | g | 0] into per-lane mma fragment order
// g_Bpack[(s*NT8 + j)*32 + lane] = {b0, b1} (fp16x2 each)
// h = j*8 + (lane>>2), k = s*16 + (lane&3)*2  (b0: k,k+1; b1: k+8,k+9)
// ============================================================
__device__ __forceinline__ float wval(const float* Wenc, const float* Watt,
                                      const float* convw, int h, int col) {
    if (col < ENC) return Wenc[(size_t)h * ENC + col];
    int cc = col - ENC;
    if (cc < KW) {
        float s = 0.f;
        #pragma unroll
        for (int c = 0; c < CONVC; c++) s += Watt[h * CONVC + c] * convw[c * KW + cc];
        return s;
    }
    return 0.f;
}

__global__ void bpack_kernel(const float* __restrict__ Wenc,
                             const float* __restrict__ Watt,
                             const float* __restrict__ convw) {
    int idx = blockIdx.x * 256 + threadIdx.x;
    if (idx >= KSTEPS * NT8 * 32) return;
    int lane = idx & 31, j = (idx >> 5) & 31, s = idx >> 10;
    int h = j * 8 + (lane >> 2);
    int k = s * 16 + (lane & 3) * 2;
    uint2 r;
    r.x = packh(wval(Wenc, Watt, convw, h, k),
                wval(Wenc, Watt, convw, h, k + 1));
    r.y = packh(wval(Wenc, Watt, convw, h, k + 8),
                wval(Wenc, Watt, convw, h, k + 9));
    g_Bpack[idx] = r;
}

// ============================================================
// energy kernel: CTA = 64 t-rows x 256 h; 8 warps (2 M x 4 N)
// single fp16 product per k16 step
// ============================================================
__global__ __launch_bounds__(256, 2)
void energy_kernel(const float* __restrict__ enc,
                   const float* __restrict__ prev,
                   const float* __restrict__ ww,
                   const float* __restrict__ wb) {
    __shared__ float wwS[HID], dbS[HID];
    __shared__ float redS[64][5];

    const int tid = threadIdx.x;
    const int b = blockIdx.y, t0 = blockIdx.x * 64;
    const int warp = tid >> 5, lane = tid & 31;
    const int warp_m = warp >> 2, warp_n = warp & 3;
    const int g = lane >> 2, tq = lane & 3;

    if (tid < HID) {
        wwS[tid] = ww[tid];
        dbS[tid] = g_dbc[b * HID + tid];
    }
    __syncthreads();

    float d[2][8][4];
    #pragma unroll
    for (int mi = 0; mi < 2; mi++)
        #pragma unroll
        for (int jj = 0; jj < 8; jj++)
            #pragma unroll
            for (int q = 0; q < 4; q++) d[mi][jj][q] = 0.f;

    const int r_base = t0 + warp_m * 32;
    const float* encB = enc + (size_t)b * Tt * ENC;

    // ---- main K loop over enc (s = 0..31) ----
    for (int s = 0; s < 32; s++) {
        const int k0 = s * 16 + tq * 2;
        uint32_t a[2][4];
        #pragma unroll
        for (int mi = 0; mi < 2; mi++) {
            const int r0 = r_base + mi * 16 + g;
            float2 v;
            v = *(const float2*)&encB[(size_t)r0 * ENC + k0];
            a[mi][0] = packh(v.x, v.y);
            v = *(const float2*)&encB[(size_t)(r0 + 8) * ENC + k0];
            a[mi][1] = packh(v.x, v.y);
            v = *(const float2*)&encB[(size_t)r0 * ENC + k0 + 8];
            a[mi][2] = packh(v.x, v.y);
            v = *(const float2*)&encB[(size_t)(r0 + 8) * ENC + k0 + 8];
            a[mi][3] = packh(v.x, v.y);
        }
        uint2 Bf[8];
        #pragma unroll
        for (int jj = 0; jj < 8; jj++)
            Bf[jj] = g_Bpack[(s * NT8 + warp_n * 8 + jj) * 32 + lane];
        #pragma unroll
        for (int mi = 0; mi < 2; mi++)
            #pragma unroll
            for (int jj = 0; jj < 8; jj++)
                mma16816(d[mi][jj], a[mi], Bf[jj].x, Bf[jj].y);
    }

    // ---- conv K chunk (s = 32..35): A cols are shifted prev window ----
    const float* prevB = prev + b * Tt;
    for (int s = 32; s < KSTEPS; s++) {
        const int k0 = s * 16 + tq * 2;
        uint32_t a[2][4];
        #pragma unroll
        for (int mi = 0; mi < 2; mi++) {
            #pragma unroll
            for (int q = 0; q < 4; q++) {
                const int row = r_base + mi * 16 + g + ((q & 1) ? 8 : 0);
                const int col = k0 + ((q >= 2) ? 8 : 0);
                float x = 0.f, y = 0.f;
                int cc = col - ENC;
                if (cc < KW) {
                    int src = row + cc - PADW;
                    if (src >= 0 && src < Tt) x = prevB[src];
                }
                if (cc + 1 < KW) {
                    int src = row + cc + 1 - PADW;
                    if (src >= 0 && src < Tt) y = prevB[src];
                }
                a[mi][q] = packh(x, y);
            }
        }
        uint2 Bf[8];
        #pragma unroll
        for (int jj = 0; jj < 8; jj++)
            Bf[jj] = g_Bpack[(s * NT8 + warp_n * 8 + jj) * 32 + lane];
        #pragma unroll
        for (int mi = 0; mi < 2; mi++)
            #pragma unroll
            for (int jj = 0; jj < 8; jj++)
                mma16816(d[mi][jj], a[mi], Bf[jj].x, Bf[jj].y);
    }

    // ---- epilogue: e(row) = sum_h ww[h]*tanh(C + dbc[h]) ----
    float ww0[8], ww1[8], db0[8], db1[8];
    #pragma unroll
    for (int jj = 0; jj < 8; jj++) {
        int h = warp_n * 64 + jj * 8 + tq * 2;
        ww0[jj] = wwS[h];     ww1[jj] = wwS[h + 1];
        db0[jj] = dbS[h];     db1[jj] = dbS[h + 1];
    }
    #pragma unroll
    for (int mi = 0; mi < 2; mi++) {
        #pragma unroll
        for (int half = 0; half < 2; half++) {
            float e = 0.f;
            #pragma unroll
            for (int jj = 0; jj < 8; jj++) {
                e += ww0[jj] * tanhf(d[mi][jj][half * 2 + 0] + db0[jj]);
                e += ww1[jj] * tanhf(d[mi][jj][half * 2 + 1] + db1[jj]);
            }
            e += __shfl_xor_sync(0xFFFFFFFFu, e, 1);
            e += __shfl_xor_sync(0xFFFFFFFFu, e, 2);
            if (tq == 0)
                redS[warp_m * 32 + mi * 16 + half * 8 + g][warp_n] = e;
        }
    }
    __syncthreads();
    if (tid < 64) {
        float e = redS[tid][0] + redS[tid][1] + redS[tid][2] + redS[tid][3];
        g_energy[b * Tt + t0 + tid] = e + wb[0];
    }
}

// ============================================================
// masked softmax over T per batch; writes att_w into out
// ============================================================
__global__ void softmax_kernel(const int* __restrict__ text_len,
                               float* __restrict__ out_w) {
    const int b = blockIdx.x;
    const int tid = threadIdx.x;  // 512
    const int len = text_len[b];
    __shared__ float sh[512];

    float m = -3.402823466e+38f;
    for (int t = tid; t < Tt; t += 512)
        if (t < len) m = fmaxf(m, g_energy[b * Tt + t]);
    sh[tid] = m; __syncthreads();
    for (int s = 256; s > 0; s >>= 1) {
        if (tid < s) sh[tid] = fmaxf(sh[tid], sh[tid + s]);
        __syncthreads();
    }
    const float M = sh[0];
    __syncthreads();

    float sum = 0.f;
    for (int t = tid; t < Tt; t += 512) {
        float e = (t < len) ? __expf(g_energy[b * Tt + t] - M) : 0.f;
        out_w[b * Tt + t] = e;
        sum += e;
    }
    sh[tid] = sum; __syncthreads();
    for (int s = 256; s > 0; s >>= 1) {
        if (tid < s) sh[tid] += sh[tid + s];
        __syncthreads();
    }
    const float inv = 1.f / sh[0];
    for (int t = tid; t < Tt; t += 512)
        out_w[b * Tt + t] *= inv;
}

// ============================================================
// att_c: deterministic two-stage reduction
// ============================================================
__global__ void attc_part_kernel(const float* __restrict__ enc,
                                 const float* __restrict__ att_w) {
    const int b = blockIdx.y, seg = blockIdx.x;
    const int c = threadIdx.x;  // 512
    const int tstart = seg * (Tt / NSEG);
    float s = 0.f;
    for (int t = tstart; t < tstart + (Tt / NSEG); t++)
        s = fmaf(enc[((size_t)b * Tt + t) * ENC + c], att_w[b * Tt + t], s);
    g_part[(seg * Bb + b) * ENC + c] = s;
}

__global__ void attc_reduce_kernel(float* __restrict__ out_c) {
    const int b = blockIdx.x;
    const int c = threadIdx.x;  // 512
    float s = 0.f;
    #pragma unroll
    for (int seg = 0; seg < NSEG; seg++)
        s += g_part[(seg * Bb + b) * ENC + c];
    out_c[b * ENC + c] = s;
}

// ============================================================
extern "C" void kernel_launch(void* const* d_in, const int* in_sizes, int n_in,
                              void* d_out, int out_size) {
    const float* enc       = (const float*)d_in[0];   // (B,T,ENC)
    const float* dec_state = (const float*)d_in[1];   // (B,DEC)
    const float* prev      = (const float*)d_in[2];   // (B,T)
    const int*   text_len  = (const int*)  d_in[3];   // (B,)
    const float* Wenc      = (const float*)d_in[4];   // (HID,ENC)
    const float* benc      = (const float*)d_in[5];   // (HID,)
    const float* Wdec      = (const float*)d_in[6];   // (HID,DEC)
    const float* Watt      = (const float*)d_in[7];   // (HID,CONV)
    const float* convw     = (const float*)d_in[8];   // (CONV,1,K)
    const float* ww        = (const float*)d_in[9];   // (1,HID)
    const float* wb        = (const float*)d_in[10];  // (1,)

    float* out   = (float*)d_out;
    float* out_c = out;                 // att_c: (B,ENC)
    float* out_w = out + Bb * ENC;      // att_w: (B,T)

    dbc_kernel<<<Bb, 256>>>(dec_state, Wdec, benc);
    bpack_kernel<<<(KSTEPS * NT8 * 32 + 255) / 256, 256>>>(Wenc, Watt, convw);
    energy_kernel<<<dim3(Tt / 64, Bb), 256>>>(enc, prev, ww, wb);
    softmax_kernel<<<Bb, 512>>>(text_len, out_w);
    attc_part_kernel<<<dim3(NSEG, Bb), ENC>>>(enc, out_w);
    attc_reduce_kernel<<<Bb, ENC>>>(out_c);
}

// round 9
// speedup vs baseline: 9.0648x; 1.2632x over previous
#include <cuda_runtime.h>
#include <cuda_fp16.h>
#include <math.h>
#include <stdint.h>

#define Bb    64
#define Tt    2048
#define ENC   512
#define DEC   1024
#define CONVC 32
#define KW    31
#define HID   256
#define PADW  15

#define KTOT   576            // 512 enc + 31 conv + 33 zero pad
#define KSTEPS 36             // KTOT / 16
#define NSEG   32

// ---------------- device scratch ----------------
__device__ float g_dbc[Bb * HID];                 // dec@Wdec^T + b_enc
__device__ uint4 g_Bp4[KSTEPS * 16 * 32];         // fp16 weights, paired n8 tiles
__device__ float g_energy[Bb * Tt];
__device__ float g_part[NSEG * Bb * ENC];

// ---------------- helpers ----------------
__device__ __forceinline__ uint32_t packh(float x, float y) {
    __half2 h = __floats2half2_rn(x, y);
    return *(uint32_t*)&h;
}
__device__ __forceinline__ uint32_t smem_u32(const void* p) {
    uint32_t a;
    asm("{ .reg .u64 t; cvta.to.shared.u64 t, %1; cvt.u32.u64 %0, t; }" : "=r"(a) : "l"(p));
    return a;
}
__device__ __forceinline__ void mma16816(float* d, const uint32_t* a,
                                         uint32_t b0, uint32_t b1) {
    asm volatile(
        "mma.sync.aligned.m16n8k16.row.col.f32.f16.f16.f32 "
        "{%0,%1,%2,%3}, {%4,%5,%6,%7}, {%8,%9}, {%0,%1,%2,%3};"
        : "+f"(d[0]), "+f"(d[1]), "+f"(d[2]), "+f"(d[3])
        : "r"(a[0]), "r"(a[1]), "r"(a[2]), "r"(a[3]), "r"(b0), "r"(b1));
}

// ============================================================
// prep: dbc[b,h] = dec_state[b]·W_dec[h] + b_enc[h]
// ============================================================
__global__ void dbc_kernel(const float* __restrict__ dec_state,
                           const float* __restrict__ Wdec,
                           const float* __restrict__ benc) {
    int b = blockIdx.x;
    int warp = threadIdx.x >> 5, lane = threadIdx.x & 31;
    for (int h = warp; h < HID; h += 8) {
        float s = 0.f;
        const float* xr = dec_state + (size_t)b * DEC;
        const float* wr = Wdec + (size_t)h * DEC;
        for (int c = lane * 4; c < DEC; c += 32 * 4) {
            float4 x = *(const float4*)&xr[c];
            float4 w = *(const float4*)&wr[c];
            s += x.x * w.x + x.y * w.y + x.z * w.z + x.w * w.w;
        }
        #pragma unroll
        for (int off = 16; off > 0; off >>= 1) s += __shfl_xor_sync(0xFFFFFFFFu, s, off);
        if (lane == 0) g_dbc[b * HID + h] = s + benc[h];
    }
}

// ============================================================
// prep: pack Wext = [W_enc | g | 0] into paired fragment order
// g_Bp4[(s*16 + pg)*32 + lane] = {jj0.b0, jj0.b1, jj1.b0, jj1.b1}
// jj0 = (pg>>2)*8 + (pg&3)*2, jj1 = jj0+1 (global n8 tiles)
// h = jj*8 + (lane>>2), k = s*16 + (lane&3)*2 (b0: k,k+1; b1: k+8,k+9)
// ============================================================
__device__ __forceinline__ float wval(const float* Wenc, const float* Watt,
                                      const float* convw, int h, int col) {
    if (col < ENC) return Wenc[(size_t)h * ENC + col];
    int cc = col - ENC;
    if (cc < KW) {
        float s = 0.f;
        #pragma unroll
        for (int c = 0; c < CONVC; c++) s += Watt[h * CONVC + c] * convw[c * KW + cc];
        return s;
    }
    return 0.f;
}

__global__ void bpack_kernel(const float* __restrict__ Wenc,
                             const float* __restrict__ Watt,
                             const float* __restrict__ convw) {
    int idx = blockIdx.x * 256 + threadIdx.x;
    if (idx >= KSTEPS * 16 * 32) return;
    int lane = idx & 31, pg = (idx >> 5) & 15, s = idx >> 9;
    int jj0 = (pg >> 2) * 8 + (pg & 3) * 2;
    int h0 = jj0 * 8 + (lane >> 2);
    int h1 = h0 + 8;
    int k = s * 16 + (lane & 3) * 2;
    uint4 r;
    r.x = packh(wval(Wenc, Watt, convw, h0, k),     wval(Wenc, Watt, convw, h0, k + 1));
    r.y = packh(wval(Wenc, Watt, convw, h0, k + 8), wval(Wenc, Watt, convw, h0, k + 9));
    r.z = packh(wval(Wenc, Watt, convw, h1, k),     wval(Wenc, Watt, convw, h1, k + 1));
    r.w = packh(wval(Wenc, Watt, convw, h1, k + 8), wval(Wenc, Watt, convw, h1, k + 9));
    g_Bp4[idx] = r;
}

// ============================================================
// energy kernel: CTA = 64 t x 256 h; 8 warps (2 M x 4 N)
// A staged via smem (double-buffered) + ldmatrix; B via paired LDG.128
// ============================================================
#define ASTRIDE 24   // halves per row (48B) -> conflict-free ldmatrix

__global__ __launch_bounds__(256, 2)
void energy_kernel(const float* __restrict__ enc,
                   const float* __restrict__ prev,
                   const float* __restrict__ ww,
                   const float* __restrict__ wb) {
    __shared__ float wwS[HID], dbS[HID];
    __shared__ float redS[64][5];
    __shared__ __align__(16) __half aS[2][64 * ASTRIDE];

    const int tid = threadIdx.x;
    const int b = blockIdx.y, t0 = blockIdx.x * 64;
    const int warp = tid >> 5, lane = tid & 31;
    const int warp_m = warp >> 2, warp_n = warp & 3;
    const int g = lane >> 2, tq = lane & 3;

    if (tid < HID) {
        wwS[tid] = ww[tid];
        dbS[tid] = g_dbc[b * HID + tid];
    }

    float d[2][8][4];
    #pragma unroll
    for (int mi = 0; mi < 2; mi++)
        #pragma unroll
        for (int jj = 0; jj < 8; jj++)
            #pragma unroll
            for (int q = 0; q < 4; q++) d[mi][jj][q] = 0.f;

    const float* encB = enc + (size_t)b * Tt * ENC;
    const float* prevB = prev + b * Tt;

    // staging thread mapping: row = tid>>2 (0..63), c0 = (tid&3)*4
    const int srow = tid >> 2, sc0 = (tid & 3) * 4;

    // ldmatrix address (per buffer): matrix m = lane>>3, inner row = lane&7
    const int lm = lane >> 3, lr = lane & 7;
    const int arow0 = warp_m * 32 + (lm & 1) * 8 + lr;   // + mi*16
    const int acol = (lm >> 1) * 8;
    uint32_t lad[2][2];
    #pragma unroll
    for (int bf = 0; bf < 2; bf++)
        #pragma unroll
        for (int mi = 0; mi < 2; mi++)
            lad[bf][mi] = smem_u32(&aS[bf][(arow0 + mi * 16) * ASTRIDE + acol]);

    // prefetch s=0
    float4 pre = *(const float4*)&encB[(size_t)(t0 + srow) * ENC + sc0];

    for (int s = 0; s < KSTEPS; s++) {
        const int buf = s & 1;
        // store staged tile
        *(uint32_t*)&aS[buf][srow * ASTRIDE + sc0]     = packh(pre.x, pre.y);
        *(uint32_t*)&aS[buf][srow * ASTRIDE + sc0 + 2] = packh(pre.z, pre.w);

        // prefetch next tile
        if (s + 1 < 32) {
            pre = *(const float4*)&encB[(size_t)(t0 + srow) * ENC + (s + 1) * 16 + sc0];
        } else if (s + 1 < KSTEPS) {
            float v[4];
            #pragma unroll
            for (int i = 0; i < 4; i++) {
                int cc = (s + 1) * 16 + sc0 + i - ENC;
                float x = 0.f;
                if (cc < KW) {
                    int src = t0 + srow + cc - PADW;
                    if (src >= 0 && src < Tt) x = prevB[src];
                }
                v[i] = x;
            }
            pre.x = v[0]; pre.y = v[1]; pre.z = v[2]; pre.w = v[3];
        }
        __syncthreads();

        // A fragments via ldmatrix
        uint32_t a[2][4];
        #pragma unroll
        for (int mi = 0; mi < 2; mi++)
            asm volatile("ldmatrix.sync.aligned.m8n8.x4.shared.b16 {%0,%1,%2,%3}, [%4];"
                : "=r"(a[mi][0]), "=r"(a[mi][1]), "=r"(a[mi][2]), "=r"(a[mi][3])
                : "r"(lad[buf][mi]));

        // B fragments (paired)
        uint4 B2[4];
        #pragma unroll
        for (int p = 0; p < 4; p++)
            B2[p] = g_Bp4[(s * 16 + warp_n * 4 + p) * 32 + lane];

        #pragma unroll
        for (int mi = 0; mi < 2; mi++)
            #pragma unroll
            for (int p = 0; p < 4; p++) {
                mma16816(d[mi][p * 2 + 0], a[mi], B2[p].x, B2[p].y);
                mma16816(d[mi][p * 2 + 1], a[mi], B2[p].z, B2[p].w);
            }
    }

    // ---- epilogue: e(row) = sum_h ww[h]*tanh(C + dbc[h]) ----
    float ww0[8], ww1[8], db0[8], db1[8];
    #pragma unroll
    for (int jj = 0; jj < 8; jj++) {
        int h = warp_n * 64 + jj * 8 + tq * 2;
        ww0[jj] = wwS[h];     ww1[jj] = wwS[h + 1];
        db0[jj] = dbS[h];     db1[jj] = dbS[h + 1];
    }
    #pragma unroll
    for (int mi = 0; mi < 2; mi++) {
        #pragma unroll
        for (int half = 0; half < 2; half++) {
            float e = 0.f;
            #pragma unroll
            for (int jj = 0; jj < 8; jj++) {
                e += ww0[jj] * tanhf(d[mi][jj][half * 2 + 0] + db0[jj]);
                e += ww1[jj] * tanhf(d[mi][jj][half * 2 + 1] + db1[jj]);
            }
            e += __shfl_xor_sync(0xFFFFFFFFu, e, 1);
            e += __shfl_xor_sync(0xFFFFFFFFu, e, 2);
            if (tq == 0)
                redS[warp_m * 32 + mi * 16 + half * 8 + g][warp_n] = e;
        }
    }
    __syncthreads();
    if (tid < 64) {
        float e = redS[tid][0] + redS[tid][1] + redS[tid][2] + redS[tid][3];
        g_energy[b * Tt + t0 + tid] = e + wb[0];
    }
}

// ============================================================
// masked softmax over T per batch; writes att_w into out
// ============================================================
__global__ void softmax_kernel(const int* __restrict__ text_len,
                               float* __restrict__ out_w) {
    const int b = blockIdx.x;
    const int tid = threadIdx.x;  // 512
    const int len = text_len[b];
    __shared__ float sh[512];

    float m = -3.402823466e+38f;
    for (int t = tid; t < Tt; t += 512)
        if (t < len) m = fmaxf(m, g_energy[b * Tt + t]);
    sh[tid] = m; __syncthreads();
    for (int s = 256; s > 0; s >>= 1) {
        if (tid < s) sh[tid] = fmaxf(sh[tid], sh[tid + s]);
        __syncthreads();
    }
    const float M = sh[0];
    __syncthreads();

    float sum = 0.f;
    for (int t = tid; t < Tt; t += 512) {
        float e = (t < len) ? __expf(g_energy[b * Tt + t] - M) : 0.f;
        out_w[b * Tt + t] = e;
        sum += e;
    }
    sh[tid] = sum; __syncthreads();
    for (int s = 256; s > 0; s >>= 1) {
        if (tid < s) sh[tid] += sh[tid + s];
        __syncthreads();
    }
    const float inv = 1.f / sh[0];
    for (int t = tid; t < Tt; t += 512)
        out_w[b * Tt + t] *= inv;
}

// ============================================================
// att_c: deterministic two-stage reduction (float4 per thread)
// ============================================================
__global__ void attc_part_kernel(const float* __restrict__ enc,
                                 const float* __restrict__ att_w) {
    const int b = blockIdx.y, seg = blockIdx.x;
    const int c4 = threadIdx.x;  // 128 threads, 4 cols each
    const int tstart = seg * (Tt / NSEG);
    float4 s = {0.f, 0.f, 0.f, 0.f};
    #pragma unroll 4
    for (int t = tstart; t < tstart + (Tt / NSEG); t++) {
        float w = att_w[b * Tt + t];
        float4 v = *(const float4*)&enc[((size_t)b * Tt + t) * ENC + c4 * 4];
        s.x = fmaf(v.x, w, s.x);
        s.y = fmaf(v.y, w, s.y);
        s.z = fmaf(v.z, w, s.z);
        s.w = fmaf(v.w, w, s.w);
    }
    *(float4*)&g_part[(seg * Bb + b) * ENC + c4 * 4] = s;
}

__global__ void attc_reduce_kernel(float* __restrict__ out_c) {
    const int b = blockIdx.x;
    const int c = threadIdx.x;  // 512
    float s = 0.f;
    #pragma unroll
    for (int seg = 0; seg < NSEG; seg++)
        s += g_part[(seg * Bb + b) * ENC + c];
    out_c[b * ENC + c] = s;
}

// ============================================================
extern "C" void kernel_launch(void* const* d_in, const int* in_sizes, int n_in,
                              void* d_out, int out_size) {
    const float* enc       = (const float*)d_in[0];   // (B,T,ENC)
    const float* dec_state = (const float*)d_in[1];   // (B,DEC)
    const float* prev      = (const float*)d_in[2];   // (B,T)
    const int*   text_len  = (const int*)  d_in[3];   // (B,)
    const float* Wenc      = (const float*)d_in[4];   // (HID,ENC)
    const float* benc      = (const float*)d_in[5];   // (HID,)
    const float* Wdec      = (const float*)d_in[6];   // (HID,DEC)
    const float* Watt      = (const float*)d_in[7];   // (HID,CONV)
    const float* convw     = (const float*)d_in[8];   // (CONV,1,K)
    const float* ww        = (const float*)d_in[9];   // (1,HID)
    const float* wb        = (const float*)d_in[10];  // (1,)

    float* out   = (float*)d_out;
    float* out_c = out;                 // att_c: (B,ENC)
    float* out_w = out + Bb * ENC;      // att_w: (B,T)

    dbc_kernel<<<Bb, 256>>>(dec_state, Wdec, benc);
    bpack_kernel<<<(KSTEPS * 16 * 32 + 255) / 256, 256>>>(Wenc, Watt, convw);
    energy_kernel<<<dim3(Tt / 64, Bb), 256>>>(enc, prev, ww, wb);
    softmax_kernel<<<Bb, 512>>>(text_len, out_w);
    attc_part_kernel<<<dim3(NSEG, Bb), 128>>>(enc, out_w);
    attc_reduce_kernel<<<Bb, ENC>>>(out_c);
}

// round 10
// speedup vs baseline: 9.2052x; 1.0155x over previous
#include <cuda_runtime.h>
#include <cuda_fp16.h>
#include <math.h>
#include <stdint.h>

#define Bb    64
#define Tt    2048
#define ENC   512
#define DEC   1024
#define CONVC 32
#define KW    31
#define HID   256
#define PADW  15

#define KTOT   576            // 512 enc + 31 conv + 33 zero pad
#define KSTEPS 36             // KTOT / 16
#define NSEG   32

// ---------------- device scratch ----------------
__device__ float g_dbc[Bb * HID];                 // dec@Wdec^T + b_enc
__device__ uint4 g_Bp4[KSTEPS * 512];             // fp16 weights, paired n8 tiles
__device__ float g_energy[Bb * Tt];
__device__ float g_part[NSEG * Bb * ENC];

// ---------------- helpers ----------------
__device__ __forceinline__ uint32_t packh(float x, float y) {
    __half2 h = __floats2half2_rn(x, y);
    return *(uint32_t*)&h;
}
__device__ __forceinline__ uint32_t smem_u32(const void* p) {
    uint32_t a;
    asm("{ .reg .u64 t; cvta.to.shared.u64 t, %1; cvt.u32.u64 %0, t; }" : "=r"(a) : "l"(p));
    return a;
}
__device__ __forceinline__ void mma16816(float* d, const uint32_t* a,
                                         uint32_t b0, uint32_t b1) {
    asm volatile(
        "mma.sync.aligned.m16n8k16.row.col.f32.f16.f16.f32 "
        "{%0,%1,%2,%3}, {%4,%5,%6,%7}, {%8,%9}, {%0,%1,%2,%3};"
        : "+f"(d[0]), "+f"(d[1]), "+f"(d[2]), "+f"(d[3])
        : "r"(a[0]), "r"(a[1]), "r"(a[2]), "r"(a[3]), "r"(b0), "r"(b1));
}

// ============================================================
// prep: dbc[b,h] = dec_state[b]·W_dec[h] + b_enc[h]
// ============================================================
__global__ void dbc_kernel(const float* __restrict__ dec_state,
                           const float* __restrict__ Wdec,
                           const float* __restrict__ benc) {
    int b = blockIdx.x;
    int warp = threadIdx.x >> 5, lane = threadIdx.x & 31;
    for (int h = warp; h < HID; h += 8) {
        float s = 0.f;
        const float* xr = dec_state + (size_t)b * DEC;
        const float* wr = Wdec + (size_t)h * DEC;
        for (int c = lane * 4; c < DEC; c += 32 * 4) {
            float4 x = *(const float4*)&xr[c];
            float4 w = *(const float4*)&wr[c];
            s += x.x * w.x + x.y * w.y + x.z * w.z + x.w * w.w;
        }
        #pragma unroll
        for (int off = 16; off > 0; off >>= 1) s += __shfl_xor_sync(0xFFFFFFFFu, s, off);
        if (lane == 0) g_dbc[b * HID + h] = s + benc[h];
    }
}

// ============================================================
// prep: pack Wext = [W_enc | g | 0] into paired fragment order
// g_Bp4[s*512 + pg*32 + lane] = {jj0.b0, jj0.b1, jj1.b0, jj1.b1}
// jj0 = (pg>>2)*8 + (pg&3)*2, jj1 = jj0+1 (global n8 tiles)
// h = jj*8 + (lane>>2), k = s*16 + (lane&3)*2 (b0: k,k+1; b1: k+8,k+9)
// ============================================================
__device__ __forceinline__ float wval(const float* Wenc, const float* Watt,
                                      const float* convw, int h, int col) {
    if (col < ENC) return Wenc[(size_t)h * ENC + col];
    int cc = col - ENC;
    if (cc < KW) {
        float s = 0.f;
        #pragma unroll
        for (int c = 0; c < CONVC; c++) s += Watt[h * CONVC + c] * convw[c * KW + cc];
        return s;
    }
    return 0.f;
}

__global__ void bpack_kernel(const float* __restrict__ Wenc,
                             const float* __restrict__ Watt,
                             const float* __restrict__ convw) {
    int idx = blockIdx.x * 256 + threadIdx.x;
    if (idx >= KSTEPS * 512) return;
    int lane = idx & 31, pg = (idx >> 5) & 15, s = idx >> 9;
    int jj0 = (pg >> 2) * 8 + (pg & 3) * 2;
    int h0 = jj0 * 8 + (lane >> 2);
    int h1 = h0 + 8;
    int k = s * 16 + (lane & 3) * 2;
    uint4 r;
    r.x = packh(wval(Wenc, Watt, convw, h0, k),     wval(Wenc, Watt, convw, h0, k + 1));
    r.y = packh(wval(Wenc, Watt, convw, h0, k + 8), wval(Wenc, Watt, convw, h0, k + 9));
    r.z = packh(wval(Wenc, Watt, convw, h1, k),     wval(Wenc, Watt, convw, h1, k + 1));
    r.w = packh(wval(Wenc, Watt, convw, h1, k + 8), wval(Wenc, Watt, convw, h1, k + 9));
    g_Bp4[idx] = r;
}

// ============================================================
// energy kernel: CTA = 64 t x 256 h; 8 warps (2 M x 4 N)
// A and B both staged via double-buffered smem; both reg-prefetched
// ============================================================
#define ASTRIDE 24   // halves per row (48B) -> conflict-free ldmatrix

__global__ __launch_bounds__(256, 2)
void energy_kernel(const float* __restrict__ enc,
                   const float* __restrict__ prev,
                   const float* __restrict__ ww,
                   const float* __restrict__ wb) {
    __shared__ float wwS[HID], dbS[HID];
    __shared__ float redS[64][5];
    __shared__ __align__(16) __half aS[2][64 * ASTRIDE];
    __shared__ __align__(16) uint4 bS[2][512];

    const int tid = threadIdx.x;
    const int b = blockIdx.y, t0 = blockIdx.x * 64;
    const int warp = tid >> 5, lane = tid & 31;
    const int warp_m = warp >> 2, warp_n = warp & 3;
    const int g = lane >> 2, tq = lane & 3;

    if (tid < HID) {
        wwS[tid] = ww[tid];
        dbS[tid] = g_dbc[b * HID + tid];
    }

    float d[2][8][4];
    #pragma unroll
    for (int mi = 0; mi < 2; mi++)
        #pragma unroll
        for (int jj = 0; jj < 8; jj++)
            #pragma unroll
            for (int q = 0; q < 4; q++) d[mi][jj][q] = 0.f;

    const float* encB = enc + (size_t)b * Tt * ENC;
    const float* prevB = prev + b * Tt;

    // staging thread mapping: row = tid>>2 (0..63), c0 = (tid&3)*4
    const int srow = tid >> 2, sc0 = (tid & 3) * 4;

    // ldmatrix address (per buffer)
    const int lm = lane >> 3, lr = lane & 7;
    const int arow0 = warp_m * 32 + (lm & 1) * 8 + lr;   // + mi*16
    const int acol = (lm >> 1) * 8;
    uint32_t lad[2][2];
    #pragma unroll
    for (int bf = 0; bf < 2; bf++)
        #pragma unroll
        for (int mi = 0; mi < 2; mi++)
            lad[bf][mi] = smem_u32(&aS[bf][(arow0 + mi * 16) * ASTRIDE + acol]);

    // prefetch s=0 (A and B)
    float4 pre = *(const float4*)&encB[(size_t)(t0 + srow) * ENC + sc0];
    uint4 bpre0 = g_Bp4[tid];
    uint4 bpre1 = g_Bp4[tid + 256];

    for (int s = 0; s < KSTEPS; s++) {
        const int buf = s & 1;
        // store staged tiles
        *(uint32_t*)&aS[buf][srow * ASTRIDE + sc0]     = packh(pre.x, pre.y);
        *(uint32_t*)&aS[buf][srow * ASTRIDE + sc0 + 2] = packh(pre.z, pre.w);
        bS[buf][tid]       = bpre0;
        bS[buf][tid + 256] = bpre1;

        // prefetch next tiles
        if (s + 1 < KSTEPS) {
            bpre0 = g_Bp4[(s + 1) * 512 + tid];
            bpre1 = g_Bp4[(s + 1) * 512 + tid + 256];
            if (s + 1 < 32) {
                pre = *(const float4*)&encB[(size_t)(t0 + srow) * ENC + (s + 1) * 16 + sc0];
            } else {
                float v[4];
                #pragma unroll
                for (int i = 0; i < 4; i++) {
                    int cc = (s + 1) * 16 + sc0 + i - ENC;
                    float x = 0.f;
                    if (cc < KW) {
                        int src = t0 + srow + cc - PADW;
                        if (src >= 0 && src < Tt) x = prevB[src];
                    }
                    v[i] = x;
                }
                pre.x = v[0]; pre.y = v[1]; pre.z = v[2]; pre.w = v[3];
            }
        }
        __syncthreads();

        // A fragments via ldmatrix
        uint32_t a[2][4];
        #pragma unroll
        for (int mi = 0; mi < 2; mi++)
            asm volatile("ldmatrix.sync.aligned.m8n8.x4.shared.b16 {%0,%1,%2,%3}, [%4];"
                : "=r"(a[mi][0]), "=r"(a[mi][1]), "=r"(a[mi][2]), "=r"(a[mi][3])
                : "r"(lad[buf][mi]));

        // B fragments from smem (paired)
        uint4 B2[4];
        #pragma unroll
        for (int p = 0; p < 4; p++)
            B2[p] = bS[buf][(warp_n * 4 + p) * 32 + lane];

        #pragma unroll
        for (int mi = 0; mi < 2; mi++)
            #pragma unroll
            for (int p = 0; p < 4; p++) {
                mma16816(d[mi][p * 2 + 0], a[mi], B2[p].x, B2[p].y);
                mma16816(d[mi][p * 2 + 1], a[mi], B2[p].z, B2[p].w);
            }
    }

    // ---- epilogue: e(row) = sum_h ww[h]*tanh(C + dbc[h]) ----
    float ww0[8], ww1[8], db0[8], db1[8];
    #pragma unroll
    for (int jj = 0; jj < 8; jj++) {
        int h = warp_n * 64 + jj * 8 + tq * 2;
        ww0[jj] = wwS[h];     ww1[jj] = wwS[h + 1];
        db0[jj] = dbS[h];     db1[jj] = dbS[h + 1];
    }
    #pragma unroll
    for (int mi = 0; mi < 2; mi++) {
        #pragma unroll
        for (int half = 0; half < 2; half++) {
            float e = 0.f;
            #pragma unroll
            for (int jj = 0; jj < 8; jj++) {
                e += ww0[jj] * tanhf(d[mi][jj][half * 2 + 0] + db0[jj]);
                e += ww1[jj] * tanhf(d[mi][jj][half * 2 + 1] + db1[jj]);
            }
            e += __shfl_xor_sync(0xFFFFFFFFu, e, 1);
            e += __shfl_xor_sync(0xFFFFFFFFu, e, 2);
            if (tq == 0)
                redS[warp_m * 32 + mi * 16 + half * 8 + g][warp_n] = e;
        }
    }
    __syncthreads();
    if (tid < 64) {
        float e = redS[tid][0] + redS[tid][1] + redS[tid][2] + redS[tid][3];
        g_energy[b * Tt + t0 + tid] = e + wb[0];
    }
}

// ============================================================
// masked softmax over T per batch; writes att_w into out
// ============================================================
__global__ void softmax_kernel(const int* __restrict__ text_len,
                               float* __restrict__ out_w) {
    const int b = blockIdx.x;
    const int tid = threadIdx.x;  // 512
    const int len = text_len[b];
    __shared__ float sh[512];

    float m = -3.402823466e+38f;
    for (int t = tid; t < Tt; t += 512)
        if (t < len) m = fmaxf(m, g_energy[b * Tt + t]);
    sh[tid] = m; __syncthreads();
    for (int s = 256; s > 0; s >>= 1) {
        if (tid < s) sh[tid] = fmaxf(sh[tid], sh[tid + s]);
        __syncthreads();
    }
    const float M = sh[0];
    __syncthreads();

    float sum = 0.f;
    for (int t = tid; t < Tt; t += 512) {
        float e = (t < len) ? __expf(g_energy[b * Tt + t] - M) : 0.f;
        out_w[b * Tt + t] = e;
        sum += e;
    }
    sh[tid] = sum; __syncthreads();
    for (int s = 256; s > 0; s >>= 1) {
        if (tid < s) sh[tid] += sh[tid + s];
        __syncthreads();
    }
    const float inv = 1.f / sh[0];
    for (int t = tid; t < Tt; t += 512)
        out_w[b * Tt + t] *= inv;
}

// ============================================================
// att_c: deterministic two-stage reduction (float4 per thread)
// ============================================================
__global__ void attc_part_kernel(const float* __restrict__ enc,
                                 const float* __restrict__ att_w) {
    const int b = blockIdx.y, seg = blockIdx.x;
    const int c4 = threadIdx.x;  // 128 threads, 4 cols each
    const int tstart = seg * (Tt / NSEG);
    float4 s = {0.f, 0.f, 0.f, 0.f};
    #pragma unroll 4
    for (int t = tstart; t < tstart + (Tt / NSEG); t++) {
        float w = att_w[b * Tt + t];
        float4 v = *(const float4*)&enc[((size_t)b * Tt + t) * ENC + c4 * 4];
        s.x = fmaf(v.x, w, s.x);
        s.y = fmaf(v.y, w, s.y);
        s.z = fmaf(v.z, w, s.z);
        s.w = fmaf(v.w, w, s.w);
    }
    *(float4*)&g_part[(seg * Bb + b) * ENC + c4 * 4] = s;
}

__global__ void attc_reduce_kernel(float* __restrict__ out_c) {
    const int b = blockIdx.x;
    const int c = threadIdx.x;  // 512
    float s = 0.f;
    #pragma unroll
    for (int seg = 0; seg < NSEG; seg++)
        s += g_part[(seg * Bb + b) * ENC + c];
    out_c[b * ENC + c] = s;
}

// ============================================================
extern "C" void kernel_launch(void* const* d_in, const int* in_sizes, int n_in,
                              void* d_out, int out_size) {
    const float* enc       = (const float*)d_in[0];   // (B,T,ENC)
    const float* dec_state = (const float*)d_in[1];   // (B,DEC)
    const float* prev      = (const float*)d_in[2];   // (B,T)
    const int*   text_len  = (const int*)  d_in[3];   // (B,)
    const float* Wenc      = (const float*)d_in[4];   // (HID,ENC)
    const float* benc      = (const float*)d_in[5];   // (HID,)
    const float* Wdec      = (const float*)d_in[6];   // (HID,DEC)
    const float* Watt      = (const float*)d_in[7];   // (HID,CONV)
    const float* convw     = (const float*)d_in[8];   // (CONV,1,K)
    const float* ww        = (const float*)d_in[9];   // (1,HID)
    const float* wb        = (const float*)d_in[10];  // (1,)

    float* out   = (float*)d_out;
    float* out_c = out;                 // att_c: (B,ENC)
    float* out_w = out + Bb * ENC;      // att_w: (B,T)

    dbc_kernel<<<Bb, 256>>>(dec_state, Wdec, benc);
    bpack_kernel<<<(KSTEPS * 512 + 255) / 256, 256>>>(Wenc, Watt, convw);
    energy_kernel<<<dim3(Tt / 64, Bb), 256>>>(enc, prev, ww, wb);
    softmax_kernel<<<Bb, 512>>>(text_len, out_w);
    attc_part_kernel<<<dim3(NSEG, Bb), 128>>>(enc, out_w);
    attc_reduce_kernel<<<Bb, ENC>>>(out_c);
}

// round 11
// speedup vs baseline: 9.3132x; 1.0117x over previous
#include <cuda_runtime.h>
#include <cuda_fp16.h>
#include <math.h>
#include <stdint.h>

#define Bb    64
#define Tt    2048
#define ENC   512
#define DEC   1024
#define CONVC 32
#define KW    31
#define HID   256
#define PADW  15

#define KTOT   576            // 512 enc + 31 conv + 33 zero pad
#define KSTEPS 36             // KTOT / 16
#define NSEG   32

// ---------------- device scratch ----------------
__device__ float g_dbc[Bb * HID];                 // dec@Wdec^T + b_enc
__device__ uint4 g_Bp4[KSTEPS * 512];             // fp16 weights, paired n8 tiles
__device__ float g_energy[Bb * Tt];
__device__ float g_part[NSEG * Bb * ENC];

// ---------------- helpers ----------------
__device__ __forceinline__ uint32_t packh(float x, float y) {
    __half2 h = __floats2half2_rn(x, y);
    return *(uint32_t*)&h;
}
__device__ __forceinline__ uint32_t smem_u32(const void* p) {
    uint32_t a;
    asm("{ .reg .u64 t; cvta.to.shared.u64 t, %1; cvt.u32.u64 %0, t; }" : "=r"(a) : "l"(p));
    return a;
}
__device__ __forceinline__ void mma16816(float* d, const uint32_t* a,
                                         uint32_t b0, uint32_t b1) {
    asm volatile(
        "mma.sync.aligned.m16n8k16.row.col.f32.f16.f16.f32 "
        "{%0,%1,%2,%3}, {%4,%5,%6,%7}, {%8,%9}, {%0,%1,%2,%3};"
        : "+f"(d[0]), "+f"(d[1]), "+f"(d[2]), "+f"(d[3])
        : "r"(a[0]), "r"(a[1]), "r"(a[2]), "r"(a[3]), "r"(b0), "r"(b1));
}
__device__ __forceinline__ void cp_async16(uint32_t dst, const void* src) {
    asm volatile("cp.async.ca.shared.global [%0], [%1], 16;" :: "r"(dst), "l"(src));
}
#define CP_COMMIT() asm volatile("cp.async.commit_group;" ::: "memory")
#define CP_WAIT1()  asm volatile("cp.async.wait_group 1;" ::: "memory")

// ============================================================
// prep: dbc[b,h] = dec_state[b]·W_dec[h] + b_enc[h]
// ============================================================
__global__ void dbc_kernel(const float* __restrict__ dec_state,
                           const float* __restrict__ Wdec,
                           const float* __restrict__ benc) {
    int b = blockIdx.x;
    int warp = threadIdx.x >> 5, lane = threadIdx.x & 31;
    for (int h = warp; h < HID; h += 8) {
        float s = 0.f;
        const float* xr = dec_state + (size_t)b * DEC;
        const float* wr = Wdec + (size_t)h * DEC;
        for (int c = lane * 4; c < DEC; c += 32 * 4) {
            float4 x = *(const float4*)&xr[c];
            float4 w = *(const float4*)&wr[c];
            s += x.x * w.x + x.y * w.y + x.z * w.z + x.w * w.w;
        }
        #pragma unroll
        for (int off = 16; off > 0; off >>= 1) s += __shfl_xor_sync(0xFFFFFFFFu, s, off);
        if (lane == 0) g_dbc[b * HID + h] = s + benc[h];
    }
}

// ============================================================
// prep: pack Wext = [W_enc | g | 0] into paired fragment order
// ============================================================
__device__ __forceinline__ float wval(const float* Wenc, const float* Watt,
                                      const float* convw, int h, int col) {
    if (col < ENC) return Wenc[(size_t)h * ENC + col];
    int cc = col - ENC;
    if (cc < KW) {
        float s = 0.f;
        #pragma unroll
        for (int c = 0; c < CONVC; c++) s += Watt[h * CONVC + c] * convw[c * KW + cc];
        return s;
    }
    return 0.f;
}

__global__ void bpack_kernel(const float* __restrict__ Wenc,
                             const float* __restrict__ Watt,
                             const float* __restrict__ convw) {
    int idx = blockIdx.x * 256 + threadIdx.x;
    if (idx >= KSTEPS * 512) return;
    int lane = idx & 31, pg = (idx >> 5) & 15, s = idx >> 9;
    int jj0 = (pg >> 2) * 8 + (pg & 3) * 2;
    int h0 = jj0 * 8 + (lane >> 2);
    int h1 = h0 + 8;
    int k = s * 16 + (lane & 3) * 2;
    uint4 r;
    r.x = packh(wval(Wenc, Watt, convw, h0, k),     wval(Wenc, Watt, convw, h0, k + 1));
    r.y = packh(wval(Wenc, Watt, convw, h0, k + 8), wval(Wenc, Watt, convw, h0, k + 9));
    r.z = packh(wval(Wenc, Watt, convw, h1, k),     wval(Wenc, Watt, convw, h1, k + 1));
    r.w = packh(wval(Wenc, Watt, convw, h1, k + 8), wval(Wenc, Watt, convw, h1, k + 9));
    g_Bp4[idx] = r;
}

// ============================================================
// energy kernel: CTA = 64 t x 256 h; 8 warps (2 M x 4 N)
// A: reg-prefetch depth 2 + double-buffered smem + ldmatrix
// B: cp.async triple-buffered smem, depth-2 lookahead
// ============================================================
#define ASTRIDE 24   // halves per row (48B) -> conflict-free ldmatrix

__global__ __launch_bounds__(256, 2)
void energy_kernel(const float* __restrict__ enc,
                   const float* __restrict__ prev,
                   const float* __restrict__ ww,
                   const float* __restrict__ wb) {
    __shared__ float wwS[HID], dbS[HID];
    __shared__ float redS[64][5];
    __shared__ __align__(16) __half aS[2][64 * ASTRIDE];
    __shared__ __align__(16) uint4 bS[3][512];

    const int tid = threadIdx.x;
    const int b = blockIdx.y, t0 = blockIdx.x * 64;
    const int warp = tid >> 5, lane = tid & 31;
    const int warp_m = warp >> 2, warp_n = warp & 3;
    const int g = lane >> 2, tq = lane & 3;

    if (tid < HID) {
        wwS[tid] = ww[tid];
        dbS[tid] = g_dbc[b * HID + tid];
    }

    float d[2][8][4];
    #pragma unroll
    for (int mi = 0; mi < 2; mi++)
        #pragma unroll
        for (int jj = 0; jj < 8; jj++)
            #pragma unroll
            for (int q = 0; q < 4; q++) d[mi][jj][q] = 0.f;

    const float* encB = enc + (size_t)b * Tt * ENC;
    const float* prevB = prev + b * Tt;

    // staging thread mapping: row = tid>>2 (0..63), c0 = (tid&3)*4
    const int srow = tid >> 2, sc0 = (tid & 3) * 4;

    // ldmatrix addresses
    const int lm = lane >> 3, lr = lane & 7;
    const int arow0 = warp_m * 32 + (lm & 1) * 8 + lr;   // + mi*16
    const int acol = (lm >> 1) * 8;
    const uint32_t lad00 = smem_u32(&aS[0][(arow0 +  0) * ASTRIDE + acol]);
    const uint32_t lad01 = smem_u32(&aS[0][(arow0 + 16) * ASTRIDE + acol]);
    const uint32_t lad10 = smem_u32(&aS[1][(arow0 +  0) * ASTRIDE + acol]);
    const uint32_t lad11 = smem_u32(&aS[1][(arow0 + 16) * ASTRIDE + acol]);

    const uint32_t bBase = smem_u32(&bS[0][0]);
    const uint32_t bOff0 = tid * 16, bOff1 = tid * 16 + 4096;

    // ---- prologue: B stages 0,1 via cp.async; A s=0,1 into regs ----
    cp_async16(bBase + bOff0, &g_Bp4[tid]);
    cp_async16(bBase + bOff1, &g_Bp4[256 + tid]);
    CP_COMMIT();
    cp_async16(bBase + 8192 + bOff0, &g_Bp4[512 + tid]);
    cp_async16(bBase + 8192 + bOff1, &g_Bp4[512 + 256 + tid]);
    CP_COMMIT();
    float4 pre0 = *(const float4*)&encB[(size_t)(t0 + srow) * ENC + sc0];
    float4 pre1 = *(const float4*)&encB[(size_t)(t0 + srow) * ENC + 16 + sc0];

    // PF: 0 = enc prefetch (s+2 < 32), 1 = conv prefetch, 2 = none
#define ENERGY_STEP(S, PRE, LADM0, LADM1, PF) do {                               \
    const int _st = (S) % 3;                                                     \
    CP_WAIT1();                                                                  \
    *(uint32_t*)&aS[(S) & 1][srow * ASTRIDE + sc0]     = packh(PRE.x, PRE.y);    \
    *(uint32_t*)&aS[(S) & 1][srow * ASTRIDE + sc0 + 2] = packh(PRE.z, PRE.w);    \
    __syncthreads();                                                             \
    uint32_t a0[4], a1[4];                                                       \
    asm volatile("ldmatrix.sync.aligned.m8n8.x4.shared.b16 {%0,%1,%2,%3}, [%4];" \
        : "=r"(a0[0]), "=r"(a0[1]), "=r"(a0[2]), "=r"(a0[3]) : "r"(LADM0));      \
    asm volatile("ldmatrix.sync.aligned.m8n8.x4.shared.b16 {%0,%1,%2,%3}, [%4];" \
        : "=r"(a1[0]), "=r"(a1[1]), "=r"(a1[2]), "=r"(a1[3]) : "r"(LADM1));      \
    uint4 B2[4];                                                                 \
    _Pragma("unroll")                                                            \
    for (int p = 0; p < 4; p++)                                                  \
        B2[p] = bS[_st][(warp_n * 4 + p) * 32 + lane];                           \
    if (PF == 0) {                                                               \
        const int _sp = (S) + 2, _st2 = _sp % 3;                                 \
        cp_async16(bBase + _st2 * 8192 + bOff0, &g_Bp4[_sp * 512 + tid]);        \
        cp_async16(bBase + _st2 * 8192 + bOff1, &g_Bp4[_sp * 512 + 256 + tid]);  \
        PRE = *(const float4*)&encB[(size_t)(t0 + srow) * ENC + _sp * 16 + sc0]; \
    } else if (PF == 1) {                                                        \
        const int _sp = (S) + 2, _st2 = _sp % 3;                                 \
        cp_async16(bBase + _st2 * 8192 + bOff0, &g_Bp4[_sp * 512 + tid]);        \
        cp_async16(bBase + _st2 * 8192 + bOff1, &g_Bp4[_sp * 512 + 256 + tid]);  \
        float _v[4];                                                             \
        _Pragma("unroll")                                                        \
        for (int i = 0; i < 4; i++) {                                            \
            int cc = _sp * 16 + sc0 + i - ENC;                                   \
            float x = 0.f;                                                       \
            if (cc < KW) {                                                       \
                int src = t0 + srow + cc - PADW;                                 \
                if (src >= 0 && src < Tt) x = prevB[src];                        \
            }                                                                    \
            _v[i] = x;                                                           \
        }                                                                        \
        PRE.x = _v[0]; PRE.y = _v[1]; PRE.z = _v[2]; PRE.w = _v[3];              \
    }                                                                            \
    CP_COMMIT();                                                                 \
    _Pragma("unroll")                                                            \
    for (int p = 0; p < 4; p++) {                                                \
        mma16816(d[0][p * 2 + 0], a0, B2[p].x, B2[p].y);                         \
        mma16816(d[0][p * 2 + 1], a0, B2[p].z, B2[p].w);                         \
        mma16816(d[1][p * 2 + 0], a1, B2[p].x, B2[p].y);                         \
        mma16816(d[1][p * 2 + 1], a1, B2[p].z, B2[p].w);                         \
    }                                                                            \
} while (0)

    // steady state: s = 0..29, prefetch s+2 is always enc
    for (int s = 0; s < 30; s += 2) {
        ENERGY_STEP(s,     pre0, lad00, lad01, 0);
        ENERGY_STEP(s + 1, pre1, lad10, lad11, 0);
    }
    // tail: conv prefetches (s+2 = 32..35), then no prefetch
    ENERGY_STEP(30, pre0, lad00, lad01, 1);
    ENERGY_STEP(31, pre1, lad10, lad11, 1);
    ENERGY_STEP(32, pre0, lad00, lad01, 1);
    ENERGY_STEP(33, pre1, lad10, lad11, 1);
    ENERGY_STEP(34, pre0, lad00, lad01, 2);
    ENERGY_STEP(35, pre1, lad10, lad11, 2);
#undef ENERGY_STEP

    // ---- epilogue: e(row) = sum_h ww[h]*tanh(C + dbc[h]) ----
    float ww0[8], ww1[8], db0[8], db1[8];
    #pragma unroll
    for (int jj = 0; jj < 8; jj++) {
        int h = warp_n * 64 + jj * 8 + tq * 2;
        ww0[jj] = wwS[h];     ww1[jj] = wwS[h + 1];
        db0[jj] = dbS[h];     db1[jj] = dbS[h + 1];
    }
    #pragma unroll
    for (int mi = 0; mi < 2; mi++) {
        #pragma unroll
        for (int half = 0; half < 2; half++) {
            float e = 0.f;
            #pragma unroll
            for (int jj = 0; jj < 8; jj++) {
                e += ww0[jj] * tanhf(d[mi][jj][half * 2 + 0] + db0[jj]);
                e += ww1[jj] * tanhf(d[mi][jj][half * 2 + 1] + db1[jj]);
            }
            e += __shfl_xor_sync(0xFFFFFFFFu, e, 1);
            e += __shfl_xor_sync(0xFFFFFFFFu, e, 2);
            if (tq == 0)
                redS[warp_m * 32 + mi * 16 + half * 8 + g][warp_n] = e;
        }
    }
    __syncthreads();
    if (tid < 64) {
        float e = redS[tid][0] + redS[tid][1] + redS[tid][2] + redS[tid][3];
        g_energy[b * Tt + t0 + tid] = e + wb[0];
    }
}

// ============================================================
// masked softmax over T per batch; writes att_w into out
// ============================================================
__global__ void softmax_kernel(const int* __restrict__ text_len,
                               float* __restrict__ out_w) {
    const int b = blockIdx.x;
    const int tid = threadIdx.x;  // 512
    const int len = text_len[b];
    __shared__ float sh[512];

    float m = -3.402823466e+38f;
    for (int t = tid; t < Tt; t += 512)
        if (t < len) m = fmaxf(m, g_energy[b * Tt + t]);
    sh[tid] = m; __syncthreads();
    for (int s = 256; s > 0; s >>= 1) {
        if (tid < s) sh[tid] = fmaxf(sh[tid], sh[tid + s]);
        __syncthreads();
    }
    const float M = sh[0];
    __syncthreads();

    float sum = 0.f;
    for (int t = tid; t < Tt; t += 512) {
        float e = (t < len) ? __expf(g_energy[b * Tt + t] - M) : 0.f;
        out_w[b * Tt + t] = e;
        sum += e;
    }
    sh[tid] = sum; __syncthreads();
    for (int s = 256; s > 0; s >>= 1) {
        if (tid < s) sh[tid] += sh[tid + s];
        __syncthreads();
    }
    const float inv = 1.f / sh[0];
    for (int t = tid; t < Tt; t += 512)
        out_w[b * Tt + t] *= inv;
}

// ============================================================
// att_c: deterministic two-stage reduction (float4 per thread)
// ============================================================
__global__ void attc_part_kernel(const float* __restrict__ enc,
                                 const float* __restrict__ att_w) {
    const int b = blockIdx.y, seg = blockIdx.x;
    const int c4 = threadIdx.x;  // 128 threads, 4 cols each
    const int tstart = seg * (Tt / NSEG);
    float4 s = {0.f, 0.f, 0.f, 0.f};
    #pragma unroll 4
    for (int t = tstart; t < tstart + (Tt / NSEG); t++) {
        float w = att_w[b * Tt + t];
        float4 v = *(const float4*)&enc[((size_t)b * Tt + t) * ENC + c4 * 4];
        s.x = fmaf(v.x, w, s.x);
        s.y = fmaf(v.y, w, s.y);
        s.z = fmaf(v.z, w, s.z);
        s.w = fmaf(v.w, w, s.w);
    }
    *(float4*)&g_part[(seg * Bb + b) * ENC + c4 * 4] = s;
}

__global__ void attc_reduce_kernel(float* __restrict__ out_c) {
    const int b = blockIdx.x;
    const int c = threadIdx.x;  // 512
    float s = 0.f;
    #pragma unroll
    for (int seg = 0; seg < NSEG; seg++)
        s += g_part[(seg * Bb + b) * ENC + c];
    out_c[b * ENC + c] = s;
}

// ============================================================
extern "C" void kernel_launch(void* const* d_in, const int* in_sizes, int n_in,
                              void* d_out, int out_size) {
    const float* enc       = (const float*)d_in[0];   // (B,T,ENC)
    const float* dec_state = (const float*)d_in[1];   // (B,DEC)
    const float* prev      = (const float*)d_in[2];   // (B,T)
    const int*   text_len  = (const int*)  d_in[3];   // (B,)
    const float* Wenc      = (const float*)d_in[4];   // (HID,ENC)
    const float* benc      = (const float*)d_in[5];   // (HID,)
    const float* Wdec      = (const float*)d_in[6];   // (HID,DEC)
    const float* Watt      = (const float*)d_in[7];   // (HID,CONV)
    const float* convw     = (const float*)d_in[8];   // (CONV,1,K)
    const float* ww        = (const float*)d_in[9];   // (1,HID)
    const float* wb        = (const float*)d_in[10];  // (1,)

    float* out   = (float*)d_out;
    float* out_c = out;                 // att_c: (B,ENC)
    float* out_w = out + Bb * ENC;      // att_w: (B,T)

    dbc_kernel<<<Bb, 256>>>(dec_state, Wdec, benc);
    bpack_kernel<<<(KSTEPS * 512 + 255) / 256, 256>>>(Wenc, Watt, convw);
    energy_kernel<<<dim3(Tt / 64, Bb), 256>>>(enc, prev, ww, wb);
    softmax_kernel<<<Bb, 512>>>(text_len, out_w);
    attc_part_kernel<<<dim3(NSEG, Bb), 128>>>(enc, out_w);
    attc_reduce_kernel<<<Bb, ENC>>>(out_c);
}